// round 1
// baseline (speedup 1.0000x reference)
#include <cuda_runtime.h>
#include <math.h>

#define BB 4
#define LL 1024
#define EE 768
#define HH 12
#define DD 64
#define HALF 512
#define FF 3072
#define MTOT (BB*LL)   // 4096

// ---------------- scratch (no allocations allowed) ----------------
__device__ float g_sn [MTOT*EE];
__device__ float g_xn [MTOT*EE];
__device__ float g_q  [MTOT*EE];
__device__ float g_k  [MTOT*EE];
__device__ float g_v  [MTOT*EE];
__device__ float g_y  [MTOT*EE];
__device__ float g_x1 [MTOT*EE];
__device__ float g_xn2[MTOT*EE];
__device__ float g_h  [MTOT*FF];
__device__ int   g_gidx[MTOT];
__device__ int   g_cnt [MTOT];

// ---------------- fuse-embed index scan ----------------
// mod_age is sorted ascending (reference sorts it at construction), so the
// stable argsort is the identity permutation; occurrence index = prefix count.
__global__ void fuse_idx_kernel(const int* __restrict__ mod_idx) {
    __shared__ int sbuf[1024];
    int b = blockIdx.x, j = threadIdx.x;
    int v = mod_idx[b*LL + j];
    int is2 = (v == 2) ? 1 : 0;
    sbuf[j] = is2;
    __syncthreads();
    #pragma unroll
    for (int off = 1; off < 1024; off <<= 1) {
        int t = (j >= off) ? sbuf[j - off] : 0;
        __syncthreads();
        sbuf[j] += t;
        __syncthreads();
    }
    int p2  = sbuf[j];                 // inclusive count of 2s in [0..j]
    int occ = is2 ? (p2 - 1) : (j - p2);
    occ = min(max(occ, 0), HALF - 1);
    g_gidx[b*LL + j] = b*HALF + occ;
}

// ---------------- prefix-length (mask) kernel ----------------
__global__ void cnt_kernel(const float* __restrict__ age,
                           const float* __restrict__ mod_age) {
    int b = blockIdx.x, q = threadIdx.x;
    float a = age[b*LL + q];
    const float* ma = mod_age + b*LL;
    int lo = 0, hi = LL;
    while (lo < hi) {
        int mid = (lo + hi) >> 1;
        if (ma[mid] <= a) lo = mid + 1; else hi = mid;
    }
    g_cnt[b*LL + q] = lo;   // number of keys with mod_age <= age[q]
}

// ---------------- LayerNorm helper (256 threads per 768-row) ----------------
__device__ __forceinline__ void ln_row(const float* __restrict__ src,
                                       const float* __restrict__ w,
                                       const float* __restrict__ bia,
                                       float* __restrict__ dst) {
    int t = threadIdx.x;
    float v0 = src[t], v1 = src[t + 256], v2 = src[t + 512];
    float s  = v0 + v1 + v2;
    float ss = fmaf(v0, v0, fmaf(v1, v1, v2 * v2));
    __shared__ float red[16];
    #pragma unroll
    for (int o = 16; o; o >>= 1) {
        s  += __shfl_xor_sync(0xffffffffu, s,  o);
        ss += __shfl_xor_sync(0xffffffffu, ss, o);
    }
    int wi = t >> 5;
    if ((t & 31) == 0) { red[wi] = s; red[8 + wi] = ss; }
    __syncthreads();
    if (t == 0) {
        float ts = 0.f, tss = 0.f;
        #pragma unroll
        for (int i = 0; i < 8; i++) { ts += red[i]; tss += red[8 + i]; }
        float mean = ts * (1.0f / 768.0f);
        float var  = tss * (1.0f / 768.0f) - mean * mean;
        red[0] = mean;
        red[1] = rsqrtf(var + 1e-5f);
    }
    __syncthreads();
    float mean = red[0], inv = red[1];
    dst[t]       = (v0 - mean) * inv * w[t]       + bia[t];
    dst[t + 256] = (v1 - mean) * inv * w[t + 256] + bia[t + 256];
    dst[t + 512] = (v2 - mean) * inv * w[t + 512] + bia[t + 512];
}

__global__ void ln_kernel(const float* __restrict__ src,
                          const float* __restrict__ w,
                          const float* __restrict__ bia,
                          float* __restrict__ dst) {
    int row = blockIdx.x;
    ln_row(src + (size_t)row * EE, w, bia, dst + (size_t)row * EE);
}

// gather mod embedding row + LN0 in one pass -> sn
__global__ void gather_ln_kernel(const int* __restrict__ mod_idx,
                                 const float* __restrict__ e2,
                                 const float* __restrict__ e3,
                                 const float* __restrict__ w,
                                 const float* __restrict__ bia,
                                 float* __restrict__ dst) {
    int row = blockIdx.x;
    int sel = mod_idx[row];
    const float* src = ((sel == 2) ? e2 : e3) + (size_t)g_gidx[row] * EE;
    ln_row(src, w, bia, dst + (size_t)row * EE);
}

// ---------------- GEMM: C[M,N] = A[M,K] @ W[N,K]^T + bias (+epilogue) -------
// EPI: 0 = bias only, 1 = bias + residual, 2 = bias + exact GELU
__device__ __forceinline__ float gelu_exact(float x) {
    return 0.5f * x * (1.0f + erff(x * 0.70710678118654752440f));
}

template <int EPI>
__global__ __launch_bounds__(256)
void gemm_kernel(const float* __restrict__ A, const float* __restrict__ W,
                 const float* __restrict__ bias, const float* __restrict__ R,
                 float* __restrict__ C, int K, int N) {
    __shared__ float As[8][128];
    __shared__ float Ws[8][128];
    int tid = threadIdx.x;
    int row = tid >> 1;
    int col = (tid & 1) << 2;
    const float* Ag = A + ((size_t)(blockIdx.y * 128 + row)) * K + col;
    const float* Wg = W + ((size_t)(blockIdx.x * 128 + row)) * K + col;
    int tx = (tid & 15) << 3;
    int ty = (tid >> 4) << 3;
    float acc[8][8];
    #pragma unroll
    for (int i = 0; i < 8; i++)
        #pragma unroll
        for (int j = 0; j < 8; j++) acc[i][j] = 0.f;

    float4 av = *(const float4*)Ag;
    float4 wv = *(const float4*)Wg;
    for (int k0 = 0; k0 < K; k0 += 8) {
        As[col + 0][row] = av.x; As[col + 1][row] = av.y;
        As[col + 2][row] = av.z; As[col + 3][row] = av.w;
        Ws[col + 0][row] = wv.x; Ws[col + 1][row] = wv.y;
        Ws[col + 2][row] = wv.z; Ws[col + 3][row] = wv.w;
        __syncthreads();
        if (k0 + 8 < K) {
            av = *(const float4*)(Ag + k0 + 8);
            wv = *(const float4*)(Wg + k0 + 8);
        }
        #pragma unroll
        for (int kk = 0; kk < 8; kk++) {
            float a[8], w8[8];
            #pragma unroll
            for (int i = 0; i < 8; i++) { a[i] = As[kk][ty + i]; w8[i] = Ws[kk][tx + i]; }
            #pragma unroll
            for (int i = 0; i < 8; i++)
                #pragma unroll
                for (int j = 0; j < 8; j++)
                    acc[i][j] = fmaf(a[i], w8[j], acc[i][j]);
        }
        __syncthreads();
    }
    int mbase = blockIdx.y * 128 + ty;
    int nbase = blockIdx.x * 128 + tx;
    #pragma unroll
    for (int i = 0; i < 8; i++) {
        size_t mrow = (size_t)(mbase + i);
        #pragma unroll
        for (int j = 0; j < 8; j++) {
            int n = nbase + j;
            float v = acc[i][j] + bias[n];
            if (EPI == 1) v += R[mrow * N + n];
            if (EPI == 2) v = gelu_exact(v);
            C[mrow * N + n] = v;
        }
    }
}

// ---------------- prefix-masked flash attention ----------------
// grid: (L/128, B*H); block: 128 threads, 1 query per thread.
__global__ __launch_bounds__(128)
void attn_kernel() {
    int bh = blockIdx.y;
    int b = bh / HH, h = bh - b * HH;
    int qrow = blockIdx.x * 128 + threadIdx.x;
    int gq = b * LL + qrow;

    float qr[DD];
    const float* Qp = g_q + (size_t)gq * EE + h * DD;
    #pragma unroll
    for (int d = 0; d < DD; d++) qr[d] = Qp[d] * 0.125f;   // 1/sqrt(64)

    int cq = g_cnt[gq];
    // age is sorted ascending -> cnt is nondecreasing -> last query has max
    int kmax = g_cnt[b * LL + blockIdx.x * 128 + 127];

    __shared__ __align__(16) float Ks[32][DD];
    __shared__ __align__(16) float Vs[32][DD];

    float m = -INFINITY, l = 0.f;
    float acc[DD];
    #pragma unroll
    for (int d = 0; d < DD; d++) acc[d] = 0.f;

    for (int k0 = 0; k0 < kmax; k0 += 32) {
        for (int idx = threadIdx.x; idx < 32 * 16; idx += 128) {
            int r = idx >> 4, c4 = (idx & 15) << 2;
            int kg = k0 + r;
            float4 kv, vv;
            if (kg < kmax) {
                size_t off = ((size_t)(b * LL + kg)) * EE + h * DD + c4;
                kv = *(const float4*)(g_k + off);
                vv = *(const float4*)(g_v + off);
            } else {
                kv = make_float4(0.f, 0.f, 0.f, 0.f);
                vv = kv;
            }
            *(float4*)&Ks[r][c4] = kv;
            *(float4*)&Vs[r][c4] = vv;
        }
        __syncthreads();

        float s[32];
        float tmax = -INFINITY;
        int jlim = cq - k0;   // keys j < jlim are valid for this query
        #pragma unroll 4
        for (int j = 0; j < 32; j++) {
            float dot = 0.f;
            const float4* kr = (const float4*)Ks[j];
            #pragma unroll
            for (int i = 0; i < 16; i++) {
                float4 kv = kr[i];
                dot = fmaf(qr[4*i+0], kv.x, dot);
                dot = fmaf(qr[4*i+1], kv.y, dot);
                dot = fmaf(qr[4*i+2], kv.z, dot);
                dot = fmaf(qr[4*i+3], kv.w, dot);
            }
            s[j] = (j < jlim) ? dot : -INFINITY;
            tmax = fmaxf(tmax, s[j]);
        }
        if (tmax > -INFINITY) {
            float mnew = fmaxf(m, tmax);
            float corr = __expf(m - mnew);   // m=-inf -> 0
            l *= corr;
            #pragma unroll
            for (int d = 0; d < DD; d++) acc[d] *= corr;
            #pragma unroll 4
            for (int j = 0; j < 32; j++) {
                float p = __expf(s[j] - mnew);
                l += p;
                const float4* vr = (const float4*)Vs[j];
                #pragma unroll
                for (int i = 0; i < 16; i++) {
                    float4 vv = vr[i];
                    acc[4*i+0] = fmaf(p, vv.x, acc[4*i+0]);
                    acc[4*i+1] = fmaf(p, vv.y, acc[4*i+1]);
                    acc[4*i+2] = fmaf(p, vv.z, acc[4*i+2]);
                    acc[4*i+3] = fmaf(p, vv.w, acc[4*i+3]);
                }
            }
            m = mnew;
        }
        __syncthreads();
    }
    float invl = (l > 0.f) ? (1.0f / l) : 0.f;   // all-masked row -> zeros
    float* Yp = g_y + (size_t)gq * EE + h * DD;
    #pragma unroll
    for (int d = 0; d < DD; d++) Yp[d] = acc[d] * invl;
}

// ---------------- launch ----------------
extern "C" void kernel_launch(void* const* d_in, const int* in_sizes, int n_in,
                              void* d_out, int out_size) {
    const float* x       = (const float*)d_in[0];
    const float* age     = (const float*)d_in[1];
    const int*   mod_idx = (const int*)  d_in[2];
    const float* mod_age = (const float*)d_in[3];
    const float* e2      = (const float*)d_in[4];
    const float* e3      = (const float*)d_in[5];
    const float* ln0w = (const float*)d_in[6];
    const float* ln0b = (const float*)d_in[7];
    const float* ln1w = (const float*)d_in[8];
    const float* ln1b = (const float*)d_in[9];
    const float* ln2w = (const float*)d_in[10];
    const float* ln2b = (const float*)d_in[11];
    const float* qw = (const float*)d_in[12];
    const float* qb = (const float*)d_in[13];
    const float* kw = (const float*)d_in[14];
    const float* kb = (const float*)d_in[15];
    const float* vw = (const float*)d_in[16];
    const float* vb = (const float*)d_in[17];
    const float* cw = (const float*)d_in[18];
    const float* cb = (const float*)d_in[19];
    const float* fcw = (const float*)d_in[20];
    const float* fcb = (const float*)d_in[21];
    const float* pw  = (const float*)d_in[22];
    const float* pb  = (const float*)d_in[23];
    float* out = (float*)d_out;

    float *sn, *xn, *q, *k, *v, *y, *x1, *xn2, *hbuf;
    cudaGetSymbolAddress((void**)&sn,  g_sn);
    cudaGetSymbolAddress((void**)&xn,  g_xn);
    cudaGetSymbolAddress((void**)&q,   g_q);
    cudaGetSymbolAddress((void**)&k,   g_k);
    cudaGetSymbolAddress((void**)&v,   g_v);
    cudaGetSymbolAddress((void**)&y,   g_y);
    cudaGetSymbolAddress((void**)&x1,  g_x1);
    cudaGetSymbolAddress((void**)&xn2, g_xn2);
    cudaGetSymbolAddress((void**)&hbuf, g_h);

    // 1. fuse-embed occurrence indices + mask prefix lengths
    fuse_idx_kernel<<<BB, 1024>>>(mod_idx);
    cnt_kernel<<<BB, 1024>>>(age, mod_age);

    // 2. LN0(gathered mod embeddings) -> sn ; LN1(x) -> xn
    gather_ln_kernel<<<MTOT, 256>>>(mod_idx, e2, e3, ln0w, ln0b, sn);
    ln_kernel<<<MTOT, 256>>>(x, ln1w, ln1b, xn);

    // 3. QKV projections
    gemm_kernel<0><<<dim3(6, 32), 256>>>(xn, qw, qb, nullptr, q, EE, EE);
    gemm_kernel<0><<<dim3(6, 32), 256>>>(sn, kw, kb, nullptr, k, EE, EE);
    gemm_kernel<0><<<dim3(6, 32), 256>>>(sn, vw, vb, nullptr, v, EE, EE);

    // 4. prefix-masked flash attention -> y
    attn_kernel<<<dim3(LL / 128, BB * HH), 128>>>();

    // 5. out projection + residual -> x1
    gemm_kernel<1><<<dim3(6, 32), 256>>>(y, cw, cb, x, x1, EE, EE);

    // 6. LN2 -> xn2 ; MLP with GELU ; proj + residual -> out
    ln_kernel<<<MTOT, 256>>>(x1, ln2w, ln2b, xn2);
    gemm_kernel<2><<<dim3(24, 32), 256>>>(xn2, fcw, fcb, nullptr, hbuf, EE, FF);
    gemm_kernel<1><<<dim3(6, 32), 256>>>(hbuf, pw, pb, x1, out, FF, EE);
}

// round 3
// speedup vs baseline: 2.2264x; 2.2264x over previous
#include <cuda_runtime.h>
#include <math.h>
#include <stdint.h>

#define BB 4
#define LL 1024
#define EE 768
#define HH 12
#define DD 64
#define HALF 512
#define FF 3072
#define MTOT (BB*LL)   // 4096

// ---------------- scratch (no allocations allowed) ----------------
__device__ float g_sn [MTOT*EE];
__device__ float g_xn [MTOT*EE];
__device__ float g_q  [MTOT*EE];
__device__ float g_k  [MTOT*EE];
__device__ float g_v  [MTOT*EE];
__device__ float g_y  [MTOT*EE];
__device__ float g_x1 [MTOT*EE];
__device__ float g_xn2[MTOT*EE];
__device__ float g_h  [MTOT*FF];
__device__ int   g_gidx[MTOT];
__device__ int   g_cnt [MTOT];

// ---------------- fuse-embed index scan ----------------
__global__ void fuse_idx_kernel(const int* __restrict__ mod_idx) {
    __shared__ int sbuf[1024];
    int b = blockIdx.x, j = threadIdx.x;
    int v = mod_idx[b*LL + j];
    int is2 = (v == 2) ? 1 : 0;
    sbuf[j] = is2;
    __syncthreads();
    #pragma unroll
    for (int off = 1; off < 1024; off <<= 1) {
        int t = (j >= off) ? sbuf[j - off] : 0;
        __syncthreads();
        sbuf[j] += t;
        __syncthreads();
    }
    int p2  = sbuf[j];
    int occ = is2 ? (p2 - 1) : (j - p2);
    occ = min(max(occ, 0), HALF - 1);
    g_gidx[b*LL + j] = b*HALF + occ;
}

// ---------------- prefix-length (mask) kernel ----------------
__global__ void cnt_kernel(const float* __restrict__ age,
                           const float* __restrict__ mod_age) {
    int b = blockIdx.x, q = threadIdx.x;
    float a = age[b*LL + q];
    const float* ma = mod_age + b*LL;
    int lo = 0, hi = LL;
    while (lo < hi) {
        int mid = (lo + hi) >> 1;
        if (ma[mid] <= a) lo = mid + 1; else hi = mid;
    }
    g_cnt[b*LL + q] = lo;
}

// ---------------- LayerNorm helper ----------------
__device__ __forceinline__ void ln_row(const float* __restrict__ src,
                                       const float* __restrict__ w,
                                       const float* __restrict__ bia,
                                       float* __restrict__ dst) {
    int t = threadIdx.x;
    float v0 = src[t], v1 = src[t + 256], v2 = src[t + 512];
    float s  = v0 + v1 + v2;
    float ss = fmaf(v0, v0, fmaf(v1, v1, v2 * v2));
    __shared__ float red[16];
    #pragma unroll
    for (int o = 16; o; o >>= 1) {
        s  += __shfl_xor_sync(0xffffffffu, s,  o);
        ss += __shfl_xor_sync(0xffffffffu, ss, o);
    }
    int wi = t >> 5;
    if ((t & 31) == 0) { red[wi] = s; red[8 + wi] = ss; }
    __syncthreads();
    if (t == 0) {
        float ts = 0.f, tss = 0.f;
        #pragma unroll
        for (int i = 0; i < 8; i++) { ts += red[i]; tss += red[8 + i]; }
        float mean = ts * (1.0f / 768.0f);
        float var  = tss * (1.0f / 768.0f) - mean * mean;
        red[0] = mean;
        red[1] = rsqrtf(var + 1e-5f);
    }
    __syncthreads();
    float mean = red[0], inv = red[1];
    dst[t]       = (v0 - mean) * inv * w[t]       + bia[t];
    dst[t + 256] = (v1 - mean) * inv * w[t + 256] + bia[t + 256];
    dst[t + 512] = (v2 - mean) * inv * w[t + 512] + bia[t + 512];
}

__global__ void ln_kernel(const float* __restrict__ src,
                          const float* __restrict__ w,
                          const float* __restrict__ bia,
                          float* __restrict__ dst) {
    int row = blockIdx.x;
    ln_row(src + (size_t)row * EE, w, bia, dst + (size_t)row * EE);
}

__global__ void gather_ln_kernel(const int* __restrict__ mod_idx,
                                 const float* __restrict__ e2,
                                 const float* __restrict__ e3,
                                 const float* __restrict__ w,
                                 const float* __restrict__ bia,
                                 float* __restrict__ dst) {
    int row = blockIdx.x;
    int sel = mod_idx[row];
    const float* src = ((sel == 2) ? e2 : e3) + (size_t)g_gidx[row] * EE;
    ln_row(src, w, bia, dst + (size_t)row * EE);
}

// =====================================================================
// mma.sync tf32 GEMM: C[M,N] = A[M,K] @ W[N,K]^T (+bias, +res/GELU)
// CTA 128x128, 8 warps (warp tile 64x32), K-chunk 32, 3-stage cp.async.
// smem layout [row][k] padded to stride 36 -> conflict-free tf32 frags.
// =====================================================================
__device__ __forceinline__ float gelu_exact(float x) {
    return 0.5f * x * (1.0f + erff(x * 0.70710678118654752440f));
}

#define NSTAGE 3
#define LDK 36
#define STG_FLOATS (2 * 128 * LDK)            // A + B per stage
#define GEMM_SMEM (NSTAGE * STG_FLOATS * 4)   // 110592 bytes

__device__ __forceinline__ void cp16(uint32_t dst, const void* src) {
    asm volatile("cp.async.cg.shared.global [%0], [%1], 16;" :: "r"(dst), "l"(src));
}

__device__ __forceinline__ void load_tile(const float* __restrict__ A,
                                          const float* __restrict__ W,
                                          int K, int tM, int tN, int k0,
                                          uint32_t sA, int tid) {
    // A: 128 rows x 32 k  (1024 float4), B likewise. 256 threads x 4 each.
    uint32_t sB = sA + 128 * LDK * 4;
    #pragma unroll
    for (int j = 0; j < 4; j++) {
        int idx = tid + j * 256;
        int row = idx >> 3, c4 = idx & 7;
        uint32_t off = (uint32_t)(row * LDK + c4 * 4) * 4;
        cp16(sA + off, A + (size_t)(tM + row) * K + k0 + c4 * 4);
        cp16(sB + off, W + (size_t)(tN + row) * K + k0 + c4 * 4);
    }
}

template <int EPI>  // 0=bias, 1=bias+residual, 2=bias+GELU
__global__ __launch_bounds__(256, 1)
void tc_gemm(const float* __restrict__ A, const float* __restrict__ W,
             const float* __restrict__ bias, const float* __restrict__ R,
             float* __restrict__ C, int K, int N) {
    extern __shared__ __align__(16) float smem[];
    uint32_t smem_b = (uint32_t)__cvta_generic_to_shared(smem);
    int tid = threadIdx.x, wid = tid >> 5, lane = tid & 31;
    int wm = wid & 1, wn = wid >> 1;           // 2 x 4 warp grid
    int gid = lane >> 2, tig = lane & 3;       // group-of-4 id, thread-in-group

    const int tM = blockIdx.y * 128, tN = blockIdx.x * 128;
    const int iters = K >> 5;

    float acc[4][4][4];
    #pragma unroll
    for (int mi = 0; mi < 4; mi++)
        #pragma unroll
        for (int ni = 0; ni < 4; ni++)
            #pragma unroll
            for (int r = 0; r < 4; r++) acc[mi][ni][r] = 0.f;

    // prologue
    #pragma unroll
    for (int s = 0; s < NSTAGE - 1; s++) {
        load_tile(A, W, K, tM, tN, s * 32, smem_b + s * STG_FLOATS * 4, tid);
        asm volatile("cp.async.commit_group;" ::: "memory");
    }

    for (int i = 0; i < iters; i++) {
        int li = i + NSTAGE - 1;
        if (li < iters)
            load_tile(A, W, K, tM, tN, li * 32,
                      smem_b + (li % NSTAGE) * STG_FLOATS * 4, tid);
        asm volatile("cp.async.commit_group;" ::: "memory");
        asm volatile("cp.async.wait_group %0;" :: "n"(NSTAGE - 1) : "memory");
        __syncthreads();

        const float* As = smem + (i % NSTAGE) * STG_FLOATS;
        const float* Bs = As + 128 * LDK;
        const float* Ap = As + (wm * 64 + gid) * LDK + tig;
        const float* Bp = Bs + (wn * 32 + gid) * LDK + tig;

        #pragma unroll
        for (int ks = 0; ks < 4; ks++) {
            int kc = ks * 8;
            uint32_t a[4][4], b[4][2];
            #pragma unroll
            for (int mi = 0; mi < 4; mi++) {
                const float* p = Ap + mi * 16 * LDK + kc;
                a[mi][0] = __float_as_uint(p[0]);
                a[mi][1] = __float_as_uint(p[8 * LDK]);
                a[mi][2] = __float_as_uint(p[4]);
                a[mi][3] = __float_as_uint(p[8 * LDK + 4]);
            }
            #pragma unroll
            for (int ni = 0; ni < 4; ni++) {
                const float* p = Bp + ni * 8 * LDK + kc;
                b[ni][0] = __float_as_uint(p[0]);
                b[ni][1] = __float_as_uint(p[4]);
            }
            #pragma unroll
            for (int mi = 0; mi < 4; mi++)
                #pragma unroll
                for (int ni = 0; ni < 4; ni++)
                    asm volatile(
                        "mma.sync.aligned.m16n8k8.row.col.f32.tf32.tf32.f32 "
                        "{%0,%1,%2,%3}, {%4,%5,%6,%7}, {%8,%9}, {%0,%1,%2,%3};"
                        : "+f"(acc[mi][ni][0]), "+f"(acc[mi][ni][1]),
                          "+f"(acc[mi][ni][2]), "+f"(acc[mi][ni][3])
                        : "r"(a[mi][0]), "r"(a[mi][1]), "r"(a[mi][2]), "r"(a[mi][3]),
                          "r"(b[ni][0]), "r"(b[ni][1]));
        }
        __syncthreads();
    }

    // epilogue: fragment layout d0,d1 @ (row=gid, col=2*tig+{0,1}), d2,d3 @ row+8
    #pragma unroll
    for (int mi = 0; mi < 4; mi++) {
        int r0 = tM + wm * 64 + mi * 16 + gid;
        #pragma unroll
        for (int ni = 0; ni < 4; ni++) {
            int c = tN + wn * 32 + ni * 8 + tig * 2;
            float bx = bias[c], by = bias[c + 1];
            float2 v0 = make_float2(acc[mi][ni][0] + bx, acc[mi][ni][1] + by);
            float2 v1 = make_float2(acc[mi][ni][2] + bx, acc[mi][ni][3] + by);
            size_t o0 = (size_t)r0 * N + c;
            size_t o1 = (size_t)(r0 + 8) * N + c;
            if (EPI == 1) {
                float2 rr0 = *(const float2*)(R + o0);
                float2 rr1 = *(const float2*)(R + o1);
                v0.x += rr0.x; v0.y += rr0.y;
                v1.x += rr1.x; v1.y += rr1.y;
            }
            if (EPI == 2) {
                v0.x = gelu_exact(v0.x); v0.y = gelu_exact(v0.y);
                v1.x = gelu_exact(v1.x); v1.y = gelu_exact(v1.y);
            }
            *(float2*)(C + o0) = v0;
            *(float2*)(C + o1) = v1;
        }
    }
}

// ---------------- prefix-masked flash attention (SIMT fp32) ----------------
__global__ __launch_bounds__(128)
void attn_kernel() {
    int bh = blockIdx.y;
    int b = bh / HH, h = bh - b * HH;
    int qrow = blockIdx.x * 128 + threadIdx.x;
    int gq = b * LL + qrow;

    float qr[DD];
    const float* Qp = g_q + (size_t)gq * EE + h * DD;
    #pragma unroll
    for (int d = 0; d < DD; d++) qr[d] = Qp[d] * 0.125f;

    int cq = g_cnt[gq];
    int kmax = g_cnt[b * LL + blockIdx.x * 128 + 127];

    __shared__ __align__(16) float Ks[32][DD];
    __shared__ __align__(16) float Vs[32][DD];

    float m = -INFINITY, l = 0.f;
    float acc[DD];
    #pragma unroll
    for (int d = 0; d < DD; d++) acc[d] = 0.f;

    for (int k0 = 0; k0 < kmax; k0 += 32) {
        for (int idx = threadIdx.x; idx < 32 * 16; idx += 128) {
            int r = idx >> 4, c4 = (idx & 15) << 2;
            int kg = k0 + r;
            float4 kv, vv;
            if (kg < kmax) {
                size_t off = ((size_t)(b * LL + kg)) * EE + h * DD + c4;
                kv = *(const float4*)(g_k + off);
                vv = *(const float4*)(g_v + off);
            } else {
                kv = make_float4(0.f, 0.f, 0.f, 0.f);
                vv = kv;
            }
            *(float4*)&Ks[r][c4] = kv;
            *(float4*)&Vs[r][c4] = vv;
        }
        __syncthreads();

        float s[32];
        float tmax = -INFINITY;
        int jlim = cq - k0;
        #pragma unroll 4
        for (int j = 0; j < 32; j++) {
            float dot = 0.f;
            const float4* kr = (const float4*)Ks[j];
            #pragma unroll
            for (int i = 0; i < 16; i++) {
                float4 kv = kr[i];
                dot = fmaf(qr[4*i+0], kv.x, dot);
                dot = fmaf(qr[4*i+1], kv.y, dot);
                dot = fmaf(qr[4*i+2], kv.z, dot);
                dot = fmaf(qr[4*i+3], kv.w, dot);
            }
            s[j] = (j < jlim) ? dot : -INFINITY;
            tmax = fmaxf(tmax, s[j]);
        }
        if (tmax > -INFINITY) {
            float mnew = fmaxf(m, tmax);
            float corr = __expf(m - mnew);
            l *= corr;
            #pragma unroll
            for (int d = 0; d < DD; d++) acc[d] *= corr;
            #pragma unroll 4
            for (int j = 0; j < 32; j++) {
                float p = __expf(s[j] - mnew);
                l += p;
                const float4* vr = (const float4*)Vs[j];
                #pragma unroll
                for (int i = 0; i < 16; i++) {
                    float4 vv = vr[i];
                    acc[4*i+0] = fmaf(p, vv.x, acc[4*i+0]);
                    acc[4*i+1] = fmaf(p, vv.y, acc[4*i+1]);
                    acc[4*i+2] = fmaf(p, vv.z, acc[4*i+2]);
                    acc[4*i+3] = fmaf(p, vv.w, acc[4*i+3]);
                }
            }
            m = mnew;
        }
        __syncthreads();
    }
    float invl = (l > 0.f) ? (1.0f / l) : 0.f;
    float* Yp = g_y + (size_t)gq * EE + h * DD;
    #pragma unroll
    for (int d = 0; d < DD; d++) Yp[d] = acc[d] * invl;
}

// ---------------- launch ----------------
extern "C" void kernel_launch(void* const* d_in, const int* in_sizes, int n_in,
                              void* d_out, int out_size) {
    const float* x       = (const float*)d_in[0];
    const float* age     = (const float*)d_in[1];
    const int*   mod_idx = (const int*)  d_in[2];
    const float* mod_age = (const float*)d_in[3];
    const float* e2      = (const float*)d_in[4];
    const float* e3      = (const float*)d_in[5];
    const float* ln0w = (const float*)d_in[6];
    const float* ln0b = (const float*)d_in[7];
    const float* ln1w = (const float*)d_in[8];
    const float* ln1b = (const float*)d_in[9];
    const float* ln2w = (const float*)d_in[10];
    const float* ln2b = (const float*)d_in[11];
    const float* qw = (const float*)d_in[12];
    const float* qb = (const float*)d_in[13];
    const float* kw = (const float*)d_in[14];
    const float* kb = (const float*)d_in[15];
    const float* vw = (const float*)d_in[16];
    const float* vb = (const float*)d_in[17];
    const float* cw = (const float*)d_in[18];
    const float* cb = (const float*)d_in[19];
    const float* fcw = (const float*)d_in[20];
    const float* fcb = (const float*)d_in[21];
    const float* pw  = (const float*)d_in[22];
    const float* pb  = (const float*)d_in[23];
    float* out = (float*)d_out;

    float *sn, *xn, *q, *k, *v, *y, *x1, *xn2, *hbuf;
    cudaGetSymbolAddress((void**)&sn,  g_sn);
    cudaGetSymbolAddress((void**)&xn,  g_xn);
    cudaGetSymbolAddress((void**)&q,   g_q);
    cudaGetSymbolAddress((void**)&k,   g_k);
    cudaGetSymbolAddress((void**)&v,   g_v);
    cudaGetSymbolAddress((void**)&y,   g_y);
    cudaGetSymbolAddress((void**)&x1,  g_x1);
    cudaGetSymbolAddress((void**)&xn2, g_xn2);
    cudaGetSymbolAddress((void**)&hbuf, g_h);

    cudaFuncSetAttribute(tc_gemm<0>, cudaFuncAttributeMaxDynamicSharedMemorySize, GEMM_SMEM);
    cudaFuncSetAttribute(tc_gemm<1>, cudaFuncAttributeMaxDynamicSharedMemorySize, GEMM_SMEM);
    cudaFuncSetAttribute(tc_gemm<2>, cudaFuncAttributeMaxDynamicSharedMemorySize, GEMM_SMEM);

    // 1. fuse-embed occurrence indices + mask prefix lengths
    fuse_idx_kernel<<<BB, 1024>>>(mod_idx);
    cnt_kernel<<<BB, 1024>>>(age, mod_age);

    // 2. LN0(gathered mod embeddings) -> sn ; LN1(x) -> xn
    gather_ln_kernel<<<MTOT, 256>>>(mod_idx, e2, e3, ln0w, ln0b, sn);
    ln_kernel<<<MTOT, 256>>>(x, ln1w, ln1b, xn);

    // 3. QKV projections (tensor-core tf32)
    tc_gemm<0><<<dim3(6, 32), 256, GEMM_SMEM>>>(xn, qw, qb, nullptr, q, EE, EE);
    tc_gemm<0><<<dim3(6, 32), 256, GEMM_SMEM>>>(sn, kw, kb, nullptr, k, EE, EE);
    tc_gemm<0><<<dim3(6, 32), 256, GEMM_SMEM>>>(sn, vw, vb, nullptr, v, EE, EE);

    // 4. prefix-masked flash attention -> y
    attn_kernel<<<dim3(LL / 128, BB * HH), 128>>>();

    // 5. out projection + residual -> x1
    tc_gemm<1><<<dim3(6, 32), 256, GEMM_SMEM>>>(y, cw, cb, x, x1, EE, EE);

    // 6. LN2 -> xn2 ; MLP with GELU ; proj + residual -> out
    ln_kernel<<<MTOT, 256>>>(x1, ln2w, ln2b, xn2);
    tc_gemm<2><<<dim3(24, 32), 256, GEMM_SMEM>>>(xn2, fcw, fcb, nullptr, hbuf, EE, FF);
    tc_gemm<1><<<dim3(6, 32), 256, GEMM_SMEM>>>(hbuf, pw, pb, x1, out, FF, EE);
}

// round 5
// speedup vs baseline: 2.4631x; 1.1063x over previous
#include <cuda_runtime.h>
#include <math.h>
#include <stdint.h>

#define BB 4
#define LL 1024
#define EE 768
#define HH 12
#define DD 64
#define HALF 512
#define FF 3072
#define MTOT (BB*LL)   // 4096

// ---------------- scratch (no allocations allowed) ----------------
__device__ float g_sn [MTOT*EE];
__device__ float g_xn [MTOT*EE];
__device__ float g_q  [MTOT*EE];
__device__ float g_k  [MTOT*EE];
__device__ float g_v  [MTOT*EE];
__device__ float g_y  [MTOT*EE];
__device__ float g_x1 [MTOT*EE];
__device__ float g_xn2[MTOT*EE];
__device__ float g_h  [MTOT*FF];
__device__ int   g_gidx[MTOT];
__device__ int   g_cnt [MTOT];
// rounded weights
__device__ float g_wq [EE*EE];
__device__ float g_wk [EE*EE];
__device__ float g_wv [EE*EE];
__device__ float g_wc [EE*EE];
__device__ float g_wfc[FF*EE];
__device__ float g_wp [EE*FF];

// round-to-nearest tf32
__device__ __forceinline__ float rtf32(float x) {
    uint32_t u;
    asm("cvt.rna.tf32.f32 %0, %1;" : "=r"(u) : "f"(x));
    return __uint_as_float(u);
}

// ---------------- weight pre-rounding ----------------
__global__ void round_w_kernel(const float* __restrict__ src,
                               float* __restrict__ dst, int n4) {
    int i = blockIdx.x * blockDim.x + threadIdx.x;
    if (i < n4) {
        float4 v = ((const float4*)src)[i];
        v.x = rtf32(v.x); v.y = rtf32(v.y);
        v.z = rtf32(v.z); v.w = rtf32(v.w);
        ((float4*)dst)[i] = v;
    }
}

// ---------------- fuse-embed index scan ----------------
__global__ void fuse_idx_kernel(const int* __restrict__ mod_idx) {
    __shared__ int sbuf[1024];
    int b = blockIdx.x, j = threadIdx.x;
    int v = mod_idx[b*LL + j];
    int is2 = (v == 2) ? 1 : 0;
    sbuf[j] = is2;
    __syncthreads();
    #pragma unroll
    for (int off = 1; off < 1024; off <<= 1) {
        int t = (j >= off) ? sbuf[j - off] : 0;
        __syncthreads();
        sbuf[j] += t;
        __syncthreads();
    }
    int p2  = sbuf[j];
    int occ = is2 ? (p2 - 1) : (j - p2);
    occ = min(max(occ, 0), HALF - 1);
    g_gidx[b*LL + j] = b*HALF + occ;
}

// ---------------- prefix-length (mask) kernel ----------------
__global__ void cnt_kernel(const float* __restrict__ age,
                           const float* __restrict__ mod_age) {
    int b = blockIdx.x, q = threadIdx.x;
    float a = age[b*LL + q];
    const float* ma = mod_age + b*LL;
    int lo = 0, hi = LL;
    while (lo < hi) {
        int mid = (lo + hi) >> 1;
        if (ma[mid] <= a) lo = mid + 1; else hi = mid;
    }
    g_cnt[b*LL + q] = lo;
}

// ---------------- LayerNorm helper (dst rounded to tf32) ----------------
__device__ __forceinline__ void ln_row(const float* __restrict__ src,
                                       const float* __restrict__ w,
                                       const float* __restrict__ bia,
                                       float* __restrict__ dst) {
    int t = threadIdx.x;
    float v0 = src[t], v1 = src[t + 256], v2 = src[t + 512];
    float s  = v0 + v1 + v2;
    float ss = fmaf(v0, v0, fmaf(v1, v1, v2 * v2));
    __shared__ float red[16];
    #pragma unroll
    for (int o = 16; o; o >>= 1) {
        s  += __shfl_xor_sync(0xffffffffu, s,  o);
        ss += __shfl_xor_sync(0xffffffffu, ss, o);
    }
    int wi = t >> 5;
    if ((t & 31) == 0) { red[wi] = s; red[8 + wi] = ss; }
    __syncthreads();
    if (t == 0) {
        float ts = 0.f, tss = 0.f;
        #pragma unroll
        for (int i = 0; i < 8; i++) { ts += red[i]; tss += red[8 + i]; }
        float mean = ts * (1.0f / 768.0f);
        float var  = tss * (1.0f / 768.0f) - mean * mean;
        red[0] = mean;
        red[1] = rsqrtf(var + 1e-5f);
    }
    __syncthreads();
    float mean = red[0], inv = red[1];
    dst[t]       = rtf32((v0 - mean) * inv * w[t]       + bia[t]);
    dst[t + 256] = rtf32((v1 - mean) * inv * w[t + 256] + bia[t + 256]);
    dst[t + 512] = rtf32((v2 - mean) * inv * w[t + 512] + bia[t + 512]);
}

__global__ void ln_kernel(const float* __restrict__ src,
                          const float* __restrict__ w,
                          const float* __restrict__ bia,
                          float* __restrict__ dst) {
    int row = blockIdx.x;
    ln_row(src + (size_t)row * EE, w, bia, dst + (size_t)row * EE);
}

__global__ void gather_ln_kernel(const int* __restrict__ mod_idx,
                                 const float* __restrict__ e2,
                                 const float* __restrict__ e3,
                                 const float* __restrict__ w,
                                 const float* __restrict__ bia,
                                 float* __restrict__ dst) {
    int row = blockIdx.x;
    int sel = mod_idx[row];
    const float* src = ((sel == 2) ? e2 : e3) + (size_t)g_gidx[row] * EE;
    ln_row(src, w, bia, dst + (size_t)row * EE);
}

// =====================================================================
// mma.sync tf32 GEMM body: C[M,N] = A[M,K] @ W[N,K]^T (+bias, +res/GELU)
// CTA 128x128, 8 warps (warp tile 64x32), K-chunk 32, 2-stage cp.async,
// 2 CTAs per SM. smem rows padded to stride 36 (conflict-free frags).
// =====================================================================
__device__ __forceinline__ float gelu_exact(float x) {
    return 0.5f * x * (1.0f + erff(x * 0.70710678118654752440f));
}

#define NSTAGE 2
#define LDK 36
#define STG_FLOATS (2 * 128 * LDK)            // A + B per stage (9216 floats)
#define GEMM_SMEM (NSTAGE * STG_FLOATS * 4)   // 73728 bytes

__device__ __forceinline__ void cp16(uint32_t dst, const void* src) {
    asm volatile("cp.async.cg.shared.global [%0], [%1], 16;" :: "r"(dst), "l"(src));
}

__device__ __forceinline__ void load_tile(const float* __restrict__ A,
                                          const float* __restrict__ W,
                                          int K, int tM, int tN, int k0,
                                          uint32_t sA, int tid) {
    uint32_t sB = sA + 128 * LDK * 4;
    #pragma unroll
    for (int j = 0; j < 4; j++) {
        int idx = tid + j * 256;
        int row = idx >> 3, c4 = idx & 7;
        uint32_t off = (uint32_t)(row * LDK + c4 * 4) * 4;
        cp16(sA + off, A + (size_t)(tM + row) * K + k0 + c4 * 4);
        cp16(sB + off, W + (size_t)(tN + row) * K + k0 + c4 * 4);
    }
}

template <int EPI>  // 0=bias, 1=bias+residual, 2=bias+GELU(rounded), 3=bias(rounded)
__device__ __forceinline__ void gemm_body(const float* __restrict__ A,
                                          const float* __restrict__ W,
                                          const float* __restrict__ bias,
                                          const float* __restrict__ R,
                                          float* __restrict__ C,
                                          int K, int N, int tM, int tN) {
    extern __shared__ __align__(16) float smem[];
    uint32_t smem_b = (uint32_t)__cvta_generic_to_shared(smem);
    int tid = threadIdx.x, wid = tid >> 5, lane = tid & 31;
    int wm = wid & 1, wn = wid >> 1;
    int gid = lane >> 2, tig = lane & 3;

    const int iters = K >> 5;

    float acc[4][4][4];
    #pragma unroll
    for (int mi = 0; mi < 4; mi++)
        #pragma unroll
        for (int ni = 0; ni < 4; ni++)
            #pragma unroll
            for (int r = 0; r < 4; r++) acc[mi][ni][r] = 0.f;

    load_tile(A, W, K, tM, tN, 0, smem_b, tid);
    asm volatile("cp.async.commit_group;" ::: "memory");

    for (int i = 0; i < iters; i++) {
        int li = i + 1;
        if (li < iters)
            load_tile(A, W, K, tM, tN, li * 32,
                      smem_b + (li & 1) * STG_FLOATS * 4, tid);
        asm volatile("cp.async.commit_group;" ::: "memory");
        asm volatile("cp.async.wait_group 1;" ::: "memory");
        __syncthreads();

        const float* As = smem + (i & 1) * STG_FLOATS;
        const float* Bs = As + 128 * LDK;
        const float* Ap = As + (wm * 64 + gid) * LDK + tig;
        const float* Bp = Bs + (wn * 32 + gid) * LDK + tig;

        #pragma unroll
        for (int ks = 0; ks < 4; ks++) {
            int kc = ks * 8;
            uint32_t a[4][4], b[4][2];
            #pragma unroll
            for (int mi = 0; mi < 4; mi++) {
                const float* p = Ap + mi * 16 * LDK + kc;
                a[mi][0] = __float_as_uint(p[0]);
                a[mi][1] = __float_as_uint(p[8 * LDK]);
                a[mi][2] = __float_as_uint(p[4]);
                a[mi][3] = __float_as_uint(p[8 * LDK + 4]);
            }
            #pragma unroll
            for (int ni = 0; ni < 4; ni++) {
                const float* p = Bp + ni * 8 * LDK + kc;
                b[ni][0] = __float_as_uint(p[0]);
                b[ni][1] = __float_as_uint(p[4]);
            }
            #pragma unroll
            for (int mi = 0; mi < 4; mi++)
                #pragma unroll
                for (int ni = 0; ni < 4; ni++)
                    asm volatile(
                        "mma.sync.aligned.m16n8k8.row.col.f32.tf32.tf32.f32 "
                        "{%0,%1,%2,%3}, {%4,%5,%6,%7}, {%8,%9}, {%0,%1,%2,%3};"
                        : "+f"(acc[mi][ni][0]), "+f"(acc[mi][ni][1]),
                          "+f"(acc[mi][ni][2]), "+f"(acc[mi][ni][3])
                        : "r"(a[mi][0]), "r"(a[mi][1]), "r"(a[mi][2]), "r"(a[mi][3]),
                          "r"(b[ni][0]), "r"(b[ni][1]));
        }
        __syncthreads();
    }

    #pragma unroll
    for (int mi = 0; mi < 4; mi++) {
        int r0 = tM + wm * 64 + mi * 16 + gid;
        #pragma unroll
        for (int ni = 0; ni < 4; ni++) {
            int c = tN + wn * 32 + ni * 8 + tig * 2;
            float bx = bias[c], by = bias[c + 1];
            float2 v0 = make_float2(acc[mi][ni][0] + bx, acc[mi][ni][1] + by);
            float2 v1 = make_float2(acc[mi][ni][2] + bx, acc[mi][ni][3] + by);
            size_t o0 = (size_t)r0 * N + c;
            size_t o1 = (size_t)(r0 + 8) * N + c;
            if (EPI == 1) {
                float2 rr0 = *(const float2*)(R + o0);
                float2 rr1 = *(const float2*)(R + o1);
                v0.x += rr0.x; v0.y += rr0.y;
                v1.x += rr1.x; v1.y += rr1.y;
            }
            if (EPI == 2) {
                v0.x = rtf32(gelu_exact(v0.x)); v0.y = rtf32(gelu_exact(v0.y));
                v1.x = rtf32(gelu_exact(v1.x)); v1.y = rtf32(gelu_exact(v1.y));
            }
            *(float2*)(C + o0) = v0;
            *(float2*)(C + o1) = v1;
        }
    }
}

template <int EPI>
__global__ __launch_bounds__(256, 2)
void tc_gemm(const float* __restrict__ A, const float* __restrict__ W,
             const float* __restrict__ bias, const float* __restrict__ R,
             float* __restrict__ C, int K, int N) {
    gemm_body<EPI>(A, W, bias, R, C, K, N, blockIdx.y * 128, blockIdx.x * 128);
}

// fused QKV: blockIdx.x in [0,18): 0-5 Q, 6-11 K, 12-17 V
__global__ __launch_bounds__(256, 2)
void qkv_gemm(const float* __restrict__ xn, const float* __restrict__ sn,
              const float* __restrict__ qb, const float* __restrict__ kb,
              const float* __restrict__ vb) {
    int part = blockIdx.x / 6;
    int bx   = blockIdx.x % 6;
    const float* A    = (part == 0) ? xn   : sn;
    const float* W    = (part == 0) ? g_wq : (part == 1) ? g_wk : g_wv;
    const float* bias = (part == 0) ? qb   : (part == 1) ? kb   : vb;
    float* C          = (part == 0) ? g_q  : (part == 1) ? g_k  : g_v;
    gemm_body<0>(A, W, bias, nullptr, C, EE, EE, blockIdx.y * 128, bx * 128);
}

// ---------------- prefix-masked flash attention (SIMT fp32) ----------------
__global__ __launch_bounds__(128)
void attn_kernel() {
    int bh = blockIdx.y;
    int b = bh / HH, h = bh - b * HH;
    int qrow = blockIdx.x * 128 + threadIdx.x;
    int gq = b * LL + qrow;

    float qr[DD];
    const float* Qp = g_q + (size_t)gq * EE + h * DD;
    #pragma unroll
    for (int d = 0; d < DD; d++) qr[d] = Qp[d] * 0.125f;

    int cq = g_cnt[gq];
    int kmax = g_cnt[b * LL + blockIdx.x * 128 + 127];

    __shared__ __align__(16) float Ks[32][DD];
    __shared__ __align__(16) float Vs[32][DD];

    float m = -INFINITY, l = 0.f;
    float acc[DD];
    #pragma unroll
    for (int d = 0; d < DD; d++) acc[d] = 0.f;

    for (int k0 = 0; k0 < kmax; k0 += 32) {
        for (int idx = threadIdx.x; idx < 32 * 16; idx += 128) {
            int r = idx >> 4, c4 = (idx & 15) << 2;
            int kg = k0 + r;
            float4 kv, vv;
            if (kg < kmax) {
                size_t off = ((size_t)(b * LL + kg)) * EE + h * DD + c4;
                kv = *(const float4*)(g_k + off);
                vv = *(const float4*)(g_v + off);
            } else {
                kv = make_float4(0.f, 0.f, 0.f, 0.f);
                vv = kv;
            }
            *(float4*)&Ks[r][c4] = kv;
            *(float4*)&Vs[r][c4] = vv;
        }
        __syncthreads();

        float s[32];
        float tmax = -INFINITY;
        int jlim = cq - k0;
        #pragma unroll 4
        for (int j = 0; j < 32; j++) {
            float dot = 0.f;
            const float4* kr = (const float4*)Ks[j];
            #pragma unroll
            for (int i = 0; i < 16; i++) {
                float4 kv = kr[i];
                dot = fmaf(qr[4*i+0], kv.x, dot);
                dot = fmaf(qr[4*i+1], kv.y, dot);
                dot = fmaf(qr[4*i+2], kv.z, dot);
                dot = fmaf(qr[4*i+3], kv.w, dot);
            }
            s[j] = (j < jlim) ? dot : -INFINITY;
            tmax = fmaxf(tmax, s[j]);
        }
        if (tmax > -INFINITY) {
            float mnew = fmaxf(m, tmax);
            float corr = __expf(m - mnew);
            l *= corr;
            #pragma unroll
            for (int d = 0; d < DD; d++) acc[d] *= corr;
            #pragma unroll 4
            for (int j = 0; j < 32; j++) {
                float p = __expf(s[j] - mnew);
                l += p;
                const float4* vr = (const float4*)Vs[j];
                #pragma unroll
                for (int i = 0; i < 16; i++) {
                    float4 vv = vr[i];
                    acc[4*i+0] = fmaf(p, vv.x, acc[4*i+0]);
                    acc[4*i+1] = fmaf(p, vv.y, acc[4*i+1]);
                    acc[4*i+2] = fmaf(p, vv.z, acc[4*i+2]);
                    acc[4*i+3] = fmaf(p, vv.w, acc[4*i+3]);
                }
            }
            m = mnew;
        }
        __syncthreads();
    }
    float invl = (l > 0.f) ? (1.0f / l) : 0.f;
    float* Yp = g_y + (size_t)gq * EE + h * DD;
    #pragma unroll
    for (int d = 0; d < DD; d++) Yp[d] = rtf32(acc[d] * invl);
}

// ---------------- launch ----------------
extern "C" void kernel_launch(void* const* d_in, const int* in_sizes, int n_in,
                              void* d_out, int out_size) {
    const float* x       = (const float*)d_in[0];
    const float* age     = (const float*)d_in[1];
    const int*   mod_idx = (const int*)  d_in[2];
    const float* mod_age = (const float*)d_in[3];
    const float* e2      = (const float*)d_in[4];
    const float* e3      = (const float*)d_in[5];
    const float* ln0w = (const float*)d_in[6];
    const float* ln0b = (const float*)d_in[7];
    const float* ln1w = (const float*)d_in[8];
    const float* ln1b = (const float*)d_in[9];
    const float* ln2w = (const float*)d_in[10];
    const float* ln2b = (const float*)d_in[11];
    const float* qw = (const float*)d_in[12];
    const float* qb = (const float*)d_in[13];
    const float* kw = (const float*)d_in[14];
    const float* kb = (const float*)d_in[15];
    const float* vw = (const float*)d_in[16];
    const float* vb = (const float*)d_in[17];
    const float* cw = (const float*)d_in[18];
    const float* cb = (const float*)d_in[19];
    const float* fcw = (const float*)d_in[20];
    const float* fcb = (const float*)d_in[21];
    const float* pw  = (const float*)d_in[22];
    const float* pb  = (const float*)d_in[23];
    float* out = (float*)d_out;

    float *sn, *xn, *y, *x1, *xn2, *hbuf;
    float *wq, *wk, *wv, *wc, *wfc, *wp;
    cudaGetSymbolAddress((void**)&sn,  g_sn);
    cudaGetSymbolAddress((void**)&xn,  g_xn);
    cudaGetSymbolAddress((void**)&y,   g_y);
    cudaGetSymbolAddress((void**)&x1,  g_x1);
    cudaGetSymbolAddress((void**)&xn2, g_xn2);
    cudaGetSymbolAddress((void**)&hbuf, g_h);
    cudaGetSymbolAddress((void**)&wq,  g_wq);
    cudaGetSymbolAddress((void**)&wk,  g_wk);
    cudaGetSymbolAddress((void**)&wv,  g_wv);
    cudaGetSymbolAddress((void**)&wc,  g_wc);
    cudaGetSymbolAddress((void**)&wfc, g_wfc);
    cudaGetSymbolAddress((void**)&wp,  g_wp);

    cudaFuncSetAttribute(tc_gemm<1>, cudaFuncAttributeMaxDynamicSharedMemorySize, GEMM_SMEM);
    cudaFuncSetAttribute(tc_gemm<2>, cudaFuncAttributeMaxDynamicSharedMemorySize, GEMM_SMEM);
    cudaFuncSetAttribute(qkv_gemm,   cudaFuncAttributeMaxDynamicSharedMemorySize, GEMM_SMEM);

    // 0. round weights to tf32 (RN) once per call
    round_w_kernel<<<(EE*EE/4 + 255)/256, 256>>>(qw, wq, EE*EE/4);
    round_w_kernel<<<(EE*EE/4 + 255)/256, 256>>>(kw, wk, EE*EE/4);
    round_w_kernel<<<(EE*EE/4 + 255)/256, 256>>>(vw, wv, EE*EE/4);
    round_w_kernel<<<(EE*EE/4 + 255)/256, 256>>>(cw, wc, EE*EE/4);
    round_w_kernel<<<(FF*EE/4 + 255)/256, 256>>>(fcw, wfc, FF*EE/4);
    round_w_kernel<<<(EE*FF/4 + 255)/256, 256>>>(pw, wp, EE*FF/4);

    // 1. fuse-embed occurrence indices + mask prefix lengths
    fuse_idx_kernel<<<BB, 1024>>>(mod_idx);
    cnt_kernel<<<BB, 1024>>>(age, mod_age);

    // 2. LN0(gathered mod embeddings) -> sn ; LN1(x) -> xn   (tf32-rounded)
    gather_ln_kernel<<<MTOT, 256>>>(mod_idx, e2, e3, ln0w, ln0b, sn);
    ln_kernel<<<MTOT, 256>>>(x, ln1w, ln1b, xn);

    // 3. fused QKV projection
    qkv_gemm<<<dim3(18, 32), 256, GEMM_SMEM>>>(xn, sn, qb, kb, vb);

    // 4. prefix-masked flash attention -> y (tf32-rounded)
    attn_kernel<<<dim3(LL / 128, BB * HH), 128>>>();

    // 5. out projection + residual -> x1
    tc_gemm<1><<<dim3(6, 32), 256, GEMM_SMEM>>>(y, wc, cb, x, x1, EE, EE);

    // 6. LN2 -> xn2 ; MLP with GELU ; proj + residual -> out
    ln_kernel<<<MTOT, 256>>>(x1, ln2w, ln2b, xn2);
    tc_gemm<2><<<dim3(24, 32), 256, GEMM_SMEM>>>(xn2, wfc, fcb, nullptr, hbuf, EE, FF);
    tc_gemm<1><<<dim3(6, 32), 256, GEMM_SMEM>>>(hbuf, wp, pb, x1, out, FF, EE);
}